// round 1
// baseline (speedup 1.0000x reference)
#include <cuda_runtime.h>
#include <cstdint>

// SlidingKVQCache: out = concat(shift(k)+key, shift(v)+value, shift(q)+query)
// Shapes: caches [B=4, H=32, S=2048, D=128] fp32; tokens [B,H,1,D].
// Pure HBM-bound copy: 768 MiB total traffic.

static constexpr int B = 4;
static constexpr int H = 32;
static constexpr int S = 2048;
static constexpr int D = 128;
static constexpr int D4 = D / 4;                 // 32 float4 per row
static constexpr long long ROWS = (long long)B * H * S;      // 262144 rows per cache
static constexpr long long CACHE_ELEMS4 = ROWS * D4;         // float4 per cache

static constexpr int ROWS_PER_BLOCK = 8;         // 256 threads = 8 warps = 8 rows

__global__ __launch_bounds__(256, 8)
void sliding_cache_shift_kernel(
    const float4* __restrict__ kc,
    const float4* __restrict__ vc,
    const float4* __restrict__ qc,
    const float4* __restrict__ kt,
    const float4* __restrict__ vt,
    const float4* __restrict__ qt,
    float4* __restrict__ out)
{
    const int c = blockIdx.y;                       // which cache (0=k,1=v,2=q)
    const float4* __restrict__ cache = (c == 0) ? kc : (c == 1) ? vc : qc;
    const float4* __restrict__ tok   = (c == 0) ? kt : (c == 1) ? vt : qt;

    const int lane = threadIdx.x & 31;              // float4 index within row
    const long long row = (long long)blockIdx.x * ROWS_PER_BLOCK + (threadIdx.x >> 5);

    const int s  = (int)(row & (S - 1));            // seq position
    const long long bh = row >> 11;                 // (b*H + h)

    const long long out_idx = (long long)c * CACHE_ELEMS4 + row * D4 + lane;

    float4 val;
    if (s < S - 1) {
        // shifted read: element one row (D floats = D4 float4) ahead
        val = cache[row * D4 + D4 + lane];
    } else {
        // last slot: new token
        val = tok[bh * D4 + lane];
    }
    out[out_idx] = val;
}

extern "C" void kernel_launch(void* const* d_in, const int* in_sizes, int n_in,
                              void* d_out, int out_size)
{
    const float4* kc = (const float4*)d_in[0];
    const float4* vc = (const float4*)d_in[1];
    const float4* qc = (const float4*)d_in[2];
    const float4* kt = (const float4*)d_in[3];
    const float4* vt = (const float4*)d_in[4];
    const float4* qt = (const float4*)d_in[5];
    float4* out = (float4*)d_out;

    dim3 grid((unsigned)(ROWS / ROWS_PER_BLOCK), 3, 1);  // 32768 x 3
    sliding_cache_shift_kernel<<<grid, 256>>>(kc, vc, qc, kt, vt, qt, out);
}

// round 2
// speedup vs baseline: 1.1383x; 1.1383x over previous
#include <cuda_runtime.h>
#include <cstdint>

// SlidingKVQCache on GB300: out = concat over {k,v,q} of (cache shifted left 1
// token, new token appended). Caches [4,32,2048,128] fp32, tokens [4,32,1,128].
//
// Flat view per cache (in float4 units): slab = 2048*32 = 65536 float4 (2^16).
//   out[i] = cache[i + 32]            if (i & 65535) <  65504
//   out[i] = tok[(i>>16)*32 + tail]   otherwise (last row of slab)
//
// Each thread copies U=4 float4 (64B), loads front-batched for MLP.

static constexpr long long SLAB4   = 65536;            // float4 per (b,h) slab
static constexpr long long SLABMASK = SLAB4 - 1;
static constexpr long long TAIL4   = SLAB4 - 32;       // 65504
static constexpr long long CACHE4  = 128LL * SLAB4;    // 8388608 float4 per cache

static constexpr int THREADS = 256;
static constexpr int U = 4;                            // float4 per thread
static constexpr long long PER_BLOCK = (long long)THREADS * U;   // 1024

__global__ __launch_bounds__(THREADS, 8)
void sliding_cache_flat_kernel(
    const float4* __restrict__ kc,
    const float4* __restrict__ vc,
    const float4* __restrict__ qc,
    const float4* __restrict__ kt,
    const float4* __restrict__ vt,
    const float4* __restrict__ qt,
    float4* __restrict__ out)
{
    const int c = blockIdx.y;
    const float4* __restrict__ cache = (c == 0) ? kc : (c == 1) ? vc : qc;
    const float4* __restrict__ tok   = (c == 0) ? kt : (c == 1) ? vt : qt;
    float4* __restrict__ ob = out + (long long)c * CACHE4;

    const long long base = (long long)blockIdx.x * PER_BLOCK + threadIdx.x;

    long long idx[U];
    const float4* __restrict__ src[U];

    #pragma unroll
    for (int k = 0; k < U; k++) {
        idx[k] = base + (long long)k * THREADS;
        long long pos = idx[k] & SLABMASK;
        // common path: shifted read from same cache; rare: token read
        src[k] = (pos < TAIL4)
               ? cache + idx[k] + 32
               : tok + ((idx[k] >> 16) << 5) + (pos - TAIL4);
    }

    float4 v[U];
    #pragma unroll
    for (int k = 0; k < U; k++) v[k] = *src[k];   // front-batched LDG.128 x4

    #pragma unroll
    for (int k = 0; k < U; k++) ob[idx[k]] = v[k];
}

extern "C" void kernel_launch(void* const* d_in, const int* in_sizes, int n_in,
                              void* d_out, int out_size)
{
    const float4* kc = (const float4*)d_in[0];
    const float4* vc = (const float4*)d_in[1];
    const float4* qc = (const float4*)d_in[2];
    const float4* kt = (const float4*)d_in[3];
    const float4* vt = (const float4*)d_in[4];
    const float4* qt = (const float4*)d_in[5];
    float4* out = (float4*)d_out;

    dim3 grid((unsigned)(CACHE4 / PER_BLOCK), 3, 1);   // 8192 x 3
    sliding_cache_flat_kernel<<<grid, THREADS>>>(kc, vc, qc, kt, vt, qt, out);
}